// round 1
// baseline (speedup 1.0000x reference)
#include <cuda_runtime.h>
#include <math.h>

#define BB 4
#define SS 512
#define EE 512
#define HH 64
#define DKK 8
#define FFNN 2048
#define MROWS (BB*SS)          // 2048
#define QKVN (3*EE)            // 1536

// ---------------- scratch (no allocations allowed) ----------------
__device__ float g_proj[MROWS*EE];      // 4 MB
__device__ float g_qkv [MROWS*QKVN];    // 12 MB
__device__ float g_ctx [MROWS*EE];      // 4 MB
__device__ float g_x1  [MROWS*EE];      // 4 MB
__device__ float g_h   [MROWS*FFNN];    // 16 MB
__device__ float g_t0  [MROWS*EE];      // 4 MB  (attn_out / ffn_out staging)

// ---------------- quantum projection == prefix product of cos ----------------
__global__ __launch_bounds__(256) void proj_kernel(const float* __restrict__ x,
                                                   float* __restrict__ p, int ngroups) {
    int g = blockIdx.x * blockDim.x + threadIdx.x;
    if (g >= ngroups) return;
    const float4* xp = (const float4*)(x + (size_t)g * 8);
    float4 a = xp[0], b = xp[1];
    float r0 = cosf(a.x);
    float r1 = r0 * cosf(a.y);
    float r2 = r1 * cosf(a.z);
    float r3 = r2 * cosf(a.w);
    float r4 = r3 * cosf(b.x);
    float r5 = r4 * cosf(b.y);
    float r6 = r5 * cosf(b.z);
    float r7 = r6 * cosf(b.w);
    float4* op = (float4*)(p + (size_t)g * 8);
    op[0] = make_float4(r0, r1, r2, r3);
    op[1] = make_float4(r4, r5, r6, r7);
}

// ---------------- generic C = A(MxK) * B(NxK)^T + bias [+res] [relu] ----------------
// BM=BN=128, BK=16, 256 threads, 8x8 per-thread. Requires M%128==0, N%128==0, K%16==0.
template<bool RELU, bool RES>
__global__ __launch_bounds__(256) void gemm_abt_kernel(
    const float* __restrict__ A, const float* __restrict__ Bm,
    const float* __restrict__ bias, const float* __restrict__ Res,
    float* __restrict__ C, int M, int N, int K)
{
    __shared__ float As[16][128];
    __shared__ float Bs[16][128];
    const int tid = threadIdx.x;
    const int tx = tid & 15;          // 0..15  (N dir)
    const int ty = tid >> 4;          // 0..15  (M dir)
    const float* Ab = A  + (size_t)blockIdx.y * 128 * K;
    const float* Bb = Bm + (size_t)blockIdx.x * 128 * K;

    float acc[8][8];
#pragma unroll
    for (int i = 0; i < 8; i++)
#pragma unroll
        for (int j = 0; j < 8; j++) acc[i][j] = 0.f;

    for (int k0 = 0; k0 < K; k0 += 16) {
#pragma unroll
        for (int i = 0; i < 2; i++) {
            int f   = tid + i * 256;       // 0..511 float4 slots
            int row = f >> 2;              // 0..127
            int c4  = (f & 3) * 4;         // 0,4,8,12
            float4 v = *(const float4*)(Ab + (size_t)row * K + k0 + c4);
            As[c4 + 0][row] = v.x; As[c4 + 1][row] = v.y;
            As[c4 + 2][row] = v.z; As[c4 + 3][row] = v.w;
            float4 w = *(const float4*)(Bb + (size_t)row * K + k0 + c4);
            Bs[c4 + 0][row] = w.x; Bs[c4 + 1][row] = w.y;
            Bs[c4 + 2][row] = w.z; Bs[c4 + 3][row] = w.w;
        }
        __syncthreads();
#pragma unroll
        for (int kk = 0; kk < 16; kk++) {
            float ra[8], rb[8];
#pragma unroll
            for (int i = 0; i < 8; i++) ra[i] = As[kk][ty * 8 + i];
#pragma unroll
            for (int j = 0; j < 8; j++) rb[j] = Bs[kk][tx * 8 + j];
#pragma unroll
            for (int i = 0; i < 8; i++)
#pragma unroll
                for (int j = 0; j < 8; j++) acc[i][j] += ra[i] * rb[j];
        }
        __syncthreads();
    }

#pragma unroll
    for (int i = 0; i < 8; i++) {
        int m = blockIdx.y * 128 + ty * 8 + i;
#pragma unroll
        for (int j4 = 0; j4 < 2; j4++) {
            int n = blockIdx.x * 128 + tx * 8 + j4 * 4;
            float4 v;
            v.x = acc[i][j4*4+0] + bias[n+0];
            v.y = acc[i][j4*4+1] + bias[n+1];
            v.z = acc[i][j4*4+2] + bias[n+2];
            v.w = acc[i][j4*4+3] + bias[n+3];
            if (RES) {
                const float4 r = *(const float4*)(Res + (size_t)m * N + n);
                v.x += r.x; v.y += r.y; v.z += r.z; v.w += r.w;
            }
            if (RELU) {
                v.x = fmaxf(v.x, 0.f); v.y = fmaxf(v.y, 0.f);
                v.z = fmaxf(v.z, 0.f); v.w = fmaxf(v.w, 0.f);
            }
            *(float4*)(C + (size_t)m * N + n) = v;
        }
    }
}

// ---------------- attention: one block per (b,h), one thread per query row ----------------
__global__ __launch_bounds__(512) void attn_kernel(const float* __restrict__ qkv,
                                                   float* __restrict__ ctx) {
    const int bh = blockIdx.x;
    const int b = bh / HH, h = bh % HH;
    __shared__ float Ks[SS][DKK];
    __shared__ float Vs[SS][DKK];
    const int t = threadIdx.x;                 // 0..511 : key row to load / query row to own
    const float* base = qkv + (size_t)b * SS * QKVN;

    {
        const float* kr = base + (size_t)t * QKVN + EE     + h * DKK;
        const float* vr = base + (size_t)t * QKVN + 2 * EE + h * DKK;
        float4 k0 = *(const float4*)kr, k1 = *(const float4*)(kr + 4);
        float4 v0 = *(const float4*)vr, v1 = *(const float4*)(vr + 4);
        Ks[t][0]=k0.x; Ks[t][1]=k0.y; Ks[t][2]=k0.z; Ks[t][3]=k0.w;
        Ks[t][4]=k1.x; Ks[t][5]=k1.y; Ks[t][6]=k1.z; Ks[t][7]=k1.w;
        Vs[t][0]=v0.x; Vs[t][1]=v0.y; Vs[t][2]=v0.z; Vs[t][3]=v0.w;
        Vs[t][4]=v1.x; Vs[t][5]=v1.y; Vs[t][6]=v1.z; Vs[t][7]=v1.w;
    }
    __syncthreads();

    float q[8];
    {
        const float* qr = base + (size_t)t * QKVN + h * DKK;
        float4 q0 = *(const float4*)qr, q1 = *(const float4*)(qr + 4);
        q[0]=q0.x; q[1]=q0.y; q[2]=q0.z; q[3]=q0.w;
        q[4]=q1.x; q[5]=q1.y; q[6]=q1.z; q[7]=q1.w;
    }
    const float sc = 0.35355339059327373f;   // 1/sqrt(8)
    float m = -1e30f, l = 0.f;
    float acc[8] = {0,0,0,0,0,0,0,0};
    for (int j = 0; j < SS; j++) {
        float s = 0.f;
#pragma unroll
        for (int d = 0; d < 8; d++) s += q[d] * Ks[j][d];
        s *= sc;
        float nm = fmaxf(m, s);
        float c  = __expf(m - nm);
        float p  = __expf(s - nm);
        l = l * c + p;
#pragma unroll
        for (int d = 0; d < 8; d++) acc[d] = acc[d] * c + p * Vs[j][d];
        m = nm;
    }
    float inv = 1.f / l;
    float* o = ctx + ((size_t)(b * SS + t)) * EE + h * DKK;
    float4 o0 = make_float4(acc[0]*inv, acc[1]*inv, acc[2]*inv, acc[3]*inv);
    float4 o1 = make_float4(acc[4]*inv, acc[5]*inv, acc[6]*inv, acc[7]*inv);
    *(float4*)o = o0; *(float4*)(o + 4) = o1;
}

// ---------------- fused residual add + layernorm over E=512, one block/row ----------------
__global__ __launch_bounds__(128) void add_ln_kernel(const float* __restrict__ a,
                                                     const float* __restrict__ r,
                                                     const float* __restrict__ w,
                                                     const float* __restrict__ bb,
                                                     float* __restrict__ out) {
    const int row = blockIdx.x;
    const int t = threadIdx.x;                 // 128 threads, 4 floats each
    const float4 av = ((const float4*)(a + (size_t)row * EE))[t];
    const float4 rv = ((const float4*)(r + (size_t)row * EE))[t];
    float v0 = av.x + rv.x, v1 = av.y + rv.y, v2 = av.z + rv.z, v3 = av.w + rv.w;

    __shared__ float sh[4];
    __shared__ float sh2[4];
    float s = v0 + v1 + v2 + v3;
#pragma unroll
    for (int o = 16; o; o >>= 1) s += __shfl_xor_sync(0xffffffffu, s, o);
    if ((t & 31) == 0) sh[t >> 5] = s;
    __syncthreads();
    const float mean = (sh[0] + sh[1] + sh[2] + sh[3]) * (1.f / 512.f);

    float d0 = v0 - mean, d1 = v1 - mean, d2 = v2 - mean, d3 = v3 - mean;
    float qsum = d0*d0 + d1*d1 + d2*d2 + d3*d3;
#pragma unroll
    for (int o = 16; o; o >>= 1) qsum += __shfl_xor_sync(0xffffffffu, qsum, o);
    if ((t & 31) == 0) sh2[t >> 5] = qsum;
    __syncthreads();
    const float var = (sh2[0] + sh2[1] + sh2[2] + sh2[3]) * (1.f / 512.f);
    const float inv = rsqrtf(var + 1e-5f);

    const float4 wv = ((const float4*)w)[t];
    const float4 bv = ((const float4*)bb)[t];
    float4 o4;
    o4.x = d0 * inv * wv.x + bv.x;
    o4.y = d1 * inv * wv.y + bv.y;
    o4.z = d2 * inv * wv.z + bv.z;
    o4.w = d3 * inv * wv.w + bv.w;
    ((float4*)(out + (size_t)row * EE))[t] = o4;
}

// ---------------- host launch ----------------
extern "C" void kernel_launch(void* const* d_in, const int* in_sizes, int n_in,
                              void* d_out, int out_size) {
    const float* x     = (const float*)d_in[0];
    const float* in_w  = (const float*)d_in[1];   // (1536,512)
    const float* in_b  = (const float*)d_in[2];
    const float* out_w = (const float*)d_in[3];   // (512,512)
    const float* out_b = (const float*)d_in[4];
    const float* ln1w  = (const float*)d_in[5];
    const float* ln1b  = (const float*)d_in[6];
    const float* ln2w  = (const float*)d_in[7];
    const float* ln2b  = (const float*)d_in[8];
    const float* w1    = (const float*)d_in[9];   // (2048,512)
    const float* b1    = (const float*)d_in[10];
    const float* w2    = (const float*)d_in[11];  // (512,2048)
    const float* b2    = (const float*)d_in[12];
    float* out = (float*)d_out;

    static float *p_proj=nullptr, *p_qkv=nullptr, *p_ctx=nullptr,
                 *p_x1=nullptr, *p_h=nullptr, *p_t0=nullptr;
    if (!p_proj) {
        cudaGetSymbolAddress((void**)&p_proj, g_proj);
        cudaGetSymbolAddress((void**)&p_qkv,  g_qkv);
        cudaGetSymbolAddress((void**)&p_ctx,  g_ctx);
        cudaGetSymbolAddress((void**)&p_x1,   g_x1);
        cudaGetSymbolAddress((void**)&p_h,    g_h);
        cudaGetSymbolAddress((void**)&p_t0,   g_t0);
    }

    const int ngroups = MROWS * EE / 8;           // 131072
    proj_kernel<<<(ngroups + 255) / 256, 256>>>(x, p_proj, ngroups);

    // qkv = proj @ in_w^T + in_b      (2048 x 1536, K=512)
    gemm_abt_kernel<false,false><<<dim3(QKVN/128, MROWS/128), 256>>>(
        p_proj, in_w, in_b, nullptr, p_qkv, MROWS, QKVN, EE);

    // attention -> ctx (B,S,E)
    attn_kernel<<<BB * HH, SS>>>(p_qkv, p_ctx);

    // attn_out = ctx @ out_w^T + out_b   -> t0
    gemm_abt_kernel<false,false><<<dim3(EE/128, MROWS/128), 256>>>(
        p_ctx, out_w, out_b, nullptr, p_t0, MROWS, EE, EE);

    // x1 = LN(x + attn_out)
    add_ln_kernel<<<MROWS, 128>>>(x, p_t0, ln1w, ln1b, p_x1);

    // h = relu(x1 @ w1^T + b1)           (2048 x 2048, K=512)
    gemm_abt_kernel<true,false><<<dim3(FFNN/128, MROWS/128), 256>>>(
        p_x1, w1, b1, nullptr, p_h, MROWS, FFNN, EE);

    // ffn_out = h @ w2^T + b2            (2048 x 512, K=2048) -> t0
    gemm_abt_kernel<false,false><<<dim3(EE/128, MROWS/128), 256>>>(
        p_h, w2, b2, nullptr, p_t0, MROWS, EE, FFNN);

    // out = LN(x1 + ffn_out)
    add_ln_kernel<<<MROWS, 128>>>(p_x1, p_t0, ln2w, ln2b, out);
    (void)in_sizes; (void)n_in; (void)out_size;
}

// round 2
// speedup vs baseline: 2.0304x; 2.0304x over previous
#include <cuda_runtime.h>
#include <cuda_bf16.h>
#include <math.h>
#include <stdint.h>

#define BBATCH 4
#define SS 512
#define EE 512
#define HH 64
#define FFNN 2048
#define MROWS 2048
#define QKVN 1536

typedef __nv_bfloat16 bf16;
typedef __nv_bfloat162 bf162;

// ---------------- scratch (__device__ globals; no allocations allowed) ----------------
__device__ bf16  g_proj_h[MROWS*EE];
__device__ bf16  g_proj_l[MROWS*EE];
__device__ float g_qkv  [MROWS*QKVN];
__device__ bf16  g_ctx_h[MROWS*EE];
__device__ bf16  g_ctx_l[MROWS*EE];
__device__ float g_x1f  [MROWS*EE];
__device__ bf16  g_x1_h [MROWS*EE];
__device__ bf16  g_x1_l [MROWS*EE];
__device__ bf16  g_hh   [MROWS*FFNN];
__device__ bf16  g_hl   [MROWS*FFNN];
__device__ float g_t0   [MROWS*EE];
#define W_INW  0
#define W_OUTW (QKVN*EE)
#define W_W1   (W_OUTW + EE*EE)
#define W_W2   (W_W1 + FFNN*EE)
#define W_TOTAL (W_W2 + EE*FFNN)
__device__ bf16  g_wh[W_TOTAL];
__device__ bf16  g_wl[W_TOTAL];

// ---------------- small helpers ----------------
__device__ __forceinline__ void split1(float v, bf16& h, bf16& l) {
    h = __float2bfloat16(v);
    l = __float2bfloat16(v - __bfloat162float(h));
}

__device__ __forceinline__ uint32_t smem_addr(const void* p) {
    return (uint32_t)__cvta_generic_to_shared(p);
}

__device__ __forceinline__ void ldm_x4(uint32_t* r, uint32_t addr) {
    asm volatile("ldmatrix.sync.aligned.m8n8.x4.shared.b16 {%0,%1,%2,%3}, [%4];"
                 : "=r"(r[0]), "=r"(r[1]), "=r"(r[2]), "=r"(r[3]) : "r"(addr));
}

__device__ __forceinline__ void mma16816(float* c, const uint32_t* a, const uint32_t* b) {
    asm volatile("mma.sync.aligned.m16n8k16.row.col.f32.bf16.bf16.f32 "
                 "{%0,%1,%2,%3},{%4,%5,%6,%7},{%8,%9},{%0,%1,%2,%3};"
                 : "+f"(c[0]), "+f"(c[1]), "+f"(c[2]), "+f"(c[3])
                 : "r"(a[0]), "r"(a[1]), "r"(a[2]), "r"(a[3]), "r"(b[0]), "r"(b[1]));
}

__device__ __forceinline__ void cpa16(uint32_t dst, const void* src) {
    asm volatile("cp.async.cg.shared.global [%0], [%1], 16;" :: "r"(dst), "l"(src));
}

// ---------------- weight split: fp32 -> bf16 hi + bf16 lo ----------------
__global__ __launch_bounds__(256) void split_kernel(const float* __restrict__ w,
                                                    bf16* __restrict__ h,
                                                    bf16* __restrict__ l, int n4) {
    int i = blockIdx.x * blockDim.x + threadIdx.x;
    if (i >= n4) return;
    float4 v = ((const float4*)w)[i];
    bf16 h0,h1,h2,h3,l0,l1,l2,l3;
    split1(v.x,h0,l0); split1(v.y,h1,l1); split1(v.z,h2,l2); split1(v.w,h3,l3);
    ((bf162*)h)[i*2+0] = bf162{h0,h1};
    ((bf162*)h)[i*2+1] = bf162{h2,h3};
    ((bf162*)l)[i*2+0] = bf162{l0,l1};
    ((bf162*)l)[i*2+1] = bf162{l2,l3};
}

// ---------------- quantum projection == prefix product of cos, split output ----------------
__global__ __launch_bounds__(256) void proj_kernel(const float* __restrict__ x,
                                                   bf16* __restrict__ ph,
                                                   bf16* __restrict__ pl, int ngroups) {
    int g = blockIdx.x * blockDim.x + threadIdx.x;
    if (g >= ngroups) return;
    const float4* xp = (const float4*)(x + (size_t)g * 8);
    float4 a = xp[0], b = xp[1];
    float r[8];
    r[0] = cosf(a.x);
    r[1] = r[0] * cosf(a.y);
    r[2] = r[1] * cosf(a.z);
    r[3] = r[2] * cosf(a.w);
    r[4] = r[3] * cosf(b.x);
    r[5] = r[4] * cosf(b.y);
    r[6] = r[5] * cosf(b.z);
    r[7] = r[6] * cosf(b.w);
    bf16 h[8], l[8];
#pragma unroll
    for (int i = 0; i < 8; i++) split1(r[i], h[i], l[i]);
    bf162* oh = (bf162*)(ph + (size_t)g * 8);
    bf162* ol = (bf162*)(pl + (size_t)g * 8);
#pragma unroll
    for (int i = 0; i < 4; i++) { oh[i] = bf162{h[2*i],h[2*i+1]}; ol[i] = bf162{l[2*i],l[2*i+1]}; }
}

// ---------------- 3xBF16 tensor-core GEMM: C = A(MxK) * B(NxK)^T + bias ----------------
// BM = MFRAG*32 (128 or 64), BN = 128, BK = 16. 256 threads = 8 warps (2 M x 4 N).
// EPI: 0 -> fp32 out; 1 -> bf16 hi/lo split out. RELU applied before epilogue write.
template<int MFRAG, int EPI, bool RELU>
__global__ __launch_bounds__(256) void gemm_mma(
    const bf16* __restrict__ Ah, const bf16* __restrict__ Al,
    const bf16* __restrict__ Bh, const bf16* __restrict__ Bl,
    const float* __restrict__ bias,
    float* __restrict__ Cf, bf16* __restrict__ Ch, bf16* __restrict__ Cl,
    int N, int K)
{
    constexpr int BM = MFRAG * 32;
    constexpr int LDSH = 24;      // padded bf16 row stride (48B), conflict-free ldmatrix
    __shared__ bf16 sAh[2][BM * LDSH];
    __shared__ bf16 sAl[2][BM * LDSH];
    __shared__ bf16 sBh[2][128 * LDSH];
    __shared__ bf16 sBl[2][128 * LDSH];

    const int tid = threadIdx.x;
    const int lane = tid & 31, wid = tid >> 5;
    const int warp_m = wid >> 2, warp_n = wid & 3;
    const int m_base = warp_m * (MFRAG * 16);
    const int n_base = warp_n * 32;
    const int blockRow = blockIdx.y * BM;
    const int blockCol = blockIdx.x * 128;

    // ldmatrix per-lane address components
    const int lg = lane >> 3, li = lane & 7;
    const int a_row = li + (lg & 1) * 8;         // + m_base + mf*16
    const int a_col = (lg >> 1) * 8;
    const int b_row = li + (lg >> 1) * 8;        // + n_base + nt*16
    const int b_col = (lg & 1) * 8;

    float acc[MFRAG][4][4];
#pragma unroll
    for (int mf = 0; mf < MFRAG; mf++)
#pragma unroll
        for (int nf = 0; nf < 4; nf++)
#pragma unroll
            for (int q = 0; q < 4; q++) acc[mf][nf][q] = 0.f;

    auto load_tile = [&](int s, int kt) {
        const int k0 = kt * 16;
        for (int c = tid; c < BM * 2; c += 256) {
            int row = c >> 1, half = c & 1;
            size_t go = (size_t)(blockRow + row) * K + k0 + half * 8;
            uint32_t so = (uint32_t)(row * LDSH + half * 8);
            cpa16(smem_addr(&sAh[s][so]), Ah + go);
            cpa16(smem_addr(&sAl[s][so]), Al + go);
        }
        {
            int row = tid >> 1, half = tid & 1;
            size_t go = (size_t)(blockCol + row) * K + k0 + half * 8;
            uint32_t so = (uint32_t)(row * LDSH + half * 8);
            cpa16(smem_addr(&sBh[s][so]), Bh + go);
            cpa16(smem_addr(&sBl[s][so]), Bl + go);
        }
    };

    const int T = K / 16;
    load_tile(0, 0);
    asm volatile("cp.async.commit_group;");

    for (int it = 0; it < T; ++it) {
        const int s = it & 1;
        if (it + 1 < T) {
            load_tile((it + 1) & 1, it + 1);
            asm volatile("cp.async.commit_group;");
            asm volatile("cp.async.wait_group 1;");
        } else {
            asm volatile("cp.async.wait_group 0;");
        }
        __syncthreads();

        uint32_t fah[MFRAG][4], fal[MFRAG][4], fbh[2][4], fbl[2][4];
#pragma unroll
        for (int mf = 0; mf < MFRAG; mf++) {
            uint32_t base = (uint32_t)((m_base + mf * 16 + a_row) * LDSH + a_col);
            ldm_x4(fah[mf], smem_addr(&sAh[s][base]));
            ldm_x4(fal[mf], smem_addr(&sAl[s][base]));
        }
#pragma unroll
        for (int nt = 0; nt < 2; nt++) {
            uint32_t base = (uint32_t)((n_base + nt * 16 + b_row) * LDSH + b_col);
            ldm_x4(fbh[nt], smem_addr(&sBh[s][base]));
            ldm_x4(fbl[nt], smem_addr(&sBl[s][base]));
        }
#pragma unroll
        for (int mf = 0; mf < MFRAG; mf++) {
#pragma unroll
            for (int nt = 0; nt < 2; nt++) {
#pragma unroll
                for (int h = 0; h < 2; h++) {
                    const int nf = nt * 2 + h;
                    uint32_t bh2[2] = { fbh[nt][2*h], fbh[nt][2*h+1] };
                    uint32_t bl2[2] = { fbl[nt][2*h], fbl[nt][2*h+1] };
                    mma16816(acc[mf][nf], fah[mf], bh2);   // hi*hi
                    mma16816(acc[mf][nf], fah[mf], bl2);   // hi*lo
                    mma16816(acc[mf][nf], fal[mf], bh2);   // lo*hi
                }
            }
        }
        __syncthreads();
    }

    // epilogue
#pragma unroll
    for (int mf = 0; mf < MFRAG; mf++) {
        const int r0 = blockRow + m_base + mf * 16 + (lane >> 2);
#pragma unroll
        for (int nf = 0; nf < 4; nf++) {
            const int col = blockCol + n_base + nf * 8 + ((lane & 3) << 1);
            const float2 bv = *(const float2*)(bias + col);
            float v0 = acc[mf][nf][0] + bv.x;
            float v1 = acc[mf][nf][1] + bv.y;
            float v2 = acc[mf][nf][2] + bv.x;
            float v3 = acc[mf][nf][3] + bv.y;
            if (RELU) {
                v0 = fmaxf(v0, 0.f); v1 = fmaxf(v1, 0.f);
                v2 = fmaxf(v2, 0.f); v3 = fmaxf(v3, 0.f);
            }
            if (EPI == 0) {
                *(float2*)(Cf + (size_t)r0 * N + col)       = make_float2(v0, v1);
                *(float2*)(Cf + (size_t)(r0 + 8) * N + col) = make_float2(v2, v3);
            } else {
                bf16 h0,h1,h2,h3,l0,l1,l2,l3;
                split1(v0,h0,l0); split1(v1,h1,l1); split1(v2,h2,l2); split1(v3,h3,l3);
                *(bf162*)(Ch + (size_t)r0 * N + col)       = bf162{h0,h1};
                *(bf162*)(Ch + (size_t)(r0 + 8) * N + col) = bf162{h2,h3};
                *(bf162*)(Cl + (size_t)r0 * N + col)       = bf162{l0,l1};
                *(bf162*)(Cl + (size_t)(r0 + 8) * N + col) = bf162{l2,l3};
            }
        }
    }
}

// ---------------- attention: one block per (b,h), one thread per query row ----------------
__global__ __launch_bounds__(512) void attn_kernel(const float* __restrict__ qkv,
                                                   bf16* __restrict__ ch,
                                                   bf16* __restrict__ cl) {
    const int bh = blockIdx.x;
    const int b = bh / HH, h = bh % HH;
    __shared__ float Ks[SS][8];
    __shared__ float Vs[SS][8];
    const int t = threadIdx.x;
    const float* base = qkv + (size_t)b * SS * QKVN;

    {
        const float* kr = base + (size_t)t * QKVN + EE     + h * 8;
        const float* vr = base + (size_t)t * QKVN + 2 * EE + h * 8;
        float4 k0 = *(const float4*)kr, k1 = *(const float4*)(kr + 4);
        float4 v0 = *(const float4*)vr, v1 = *(const float4*)(vr + 4);
        Ks[t][0]=k0.x; Ks[t][1]=k0.y; Ks[t][2]=k0.z; Ks[t][3]=k0.w;
        Ks[t][4]=k1.x; Ks[t][5]=k1.y; Ks[t][6]=k1.z; Ks[t][7]=k1.w;
        Vs[t][0]=v0.x; Vs[t][1]=v0.y; Vs[t][2]=v0.z; Vs[t][3]=v0.w;
        Vs[t][4]=v1.x; Vs[t][5]=v1.y; Vs[t][6]=v1.z; Vs[t][7]=v1.w;
    }
    __syncthreads();

    float q[8];
    {
        const float* qr = base + (size_t)t * QKVN + h * 8;
        float4 q0 = *(const float4*)qr, q1 = *(const float4*)(qr + 4);
        q[0]=q0.x; q[1]=q0.y; q[2]=q0.z; q[3]=q0.w;
        q[4]=q1.x; q[5]=q1.y; q[6]=q1.z; q[7]=q1.w;
    }
    const float sc = 0.35355339059327373f;   // 1/sqrt(8)
    float m = -1e30f, l = 0.f;
    float acc[8] = {0,0,0,0,0,0,0,0};
    for (int j = 0; j < SS; j++) {
        float s = 0.f;
#pragma unroll
        for (int d = 0; d < 8; d++) s += q[d] * Ks[j][d];
        s *= sc;
        float nm = fmaxf(m, s);
        float c  = __expf(m - nm);
        float p  = __expf(s - nm);
        l = l * c + p;
#pragma unroll
        for (int d = 0; d < 8; d++) acc[d] = acc[d] * c + p * Vs[j][d];
        m = nm;
    }
    const float inv = 1.f / l;
    const size_t o = (size_t)(b * SS + t) * EE + h * 8;
    bf16 oh[8], ol[8];
#pragma unroll
    for (int d = 0; d < 8; d++) split1(acc[d] * inv, oh[d], ol[d]);
#pragma unroll
    for (int i = 0; i < 4; i++) {
        *(bf162*)(ch + o + 2*i) = bf162{oh[2*i], oh[2*i+1]};
        *(bf162*)(cl + o + 2*i) = bf162{ol[2*i], ol[2*i+1]};
    }
}

// ---------------- fused residual add + layernorm over E=512 ----------------
template<bool SPLIT>
__global__ __launch_bounds__(128) void add_ln_kernel(const float* __restrict__ a,
                                                     const float* __restrict__ r,
                                                     const float* __restrict__ w,
                                                     const float* __restrict__ bb,
                                                     float* __restrict__ out,
                                                     bf16* __restrict__ oh,
                                                     bf16* __restrict__ ol) {
    const int row = blockIdx.x;
    const int t = threadIdx.x;
    const float4 av = ((const float4*)(a + (size_t)row * EE))[t];
    const float4 rv = ((const float4*)(r + (size_t)row * EE))[t];
    float v0 = av.x + rv.x, v1 = av.y + rv.y, v2 = av.z + rv.z, v3 = av.w + rv.w;

    __shared__ float sh[4];
    __shared__ float sh2[4];
    float s = v0 + v1 + v2 + v3;
#pragma unroll
    for (int o = 16; o; o >>= 1) s += __shfl_xor_sync(0xffffffffu, s, o);
    if ((t & 31) == 0) sh[t >> 5] = s;
    __syncthreads();
    const float mean = (sh[0] + sh[1] + sh[2] + sh[3]) * (1.f / 512.f);

    float d0 = v0 - mean, d1 = v1 - mean, d2 = v2 - mean, d3 = v3 - mean;
    float qsum = d0*d0 + d1*d1 + d2*d2 + d3*d3;
#pragma unroll
    for (int o = 16; o; o >>= 1) qsum += __shfl_xor_sync(0xffffffffu, qsum, o);
    if ((t & 31) == 0) sh2[t >> 5] = qsum;
    __syncthreads();
    const float var = (sh2[0] + sh2[1] + sh2[2] + sh2[3]) * (1.f / 512.f);
    const float inv = rsqrtf(var + 1e-5f);

    const float4 wv = ((const float4*)w)[t];
    const float4 bv = ((const float4*)bb)[t];
    float o0 = d0 * inv * wv.x + bv.x;
    float o1 = d1 * inv * wv.y + bv.y;
    float o2 = d2 * inv * wv.z + bv.z;
    float o3 = d3 * inv * wv.w + bv.w;
    ((float4*)(out + (size_t)row * EE))[t] = make_float4(o0, o1, o2, o3);
    if (SPLIT) {
        bf16 h0,h1,h2,h3,l0,l1,l2,l3;
        split1(o0,h0,l0); split1(o1,h1,l1); split1(o2,h2,l2); split1(o3,h3,l3);
        bf162* ph = (bf162*)(oh + (size_t)row * EE + t * 4);
        bf162* pl = (bf162*)(ol + (size_t)row * EE + t * 4);
        ph[0] = bf162{h0,h1}; ph[1] = bf162{h2,h3};
        pl[0] = bf162{l0,l1}; pl[1] = bf162{l2,l3};
    }
}

// ---------------- host launch ----------------
extern "C" void kernel_launch(void* const* d_in, const int* in_sizes, int n_in,
                              void* d_out, int out_size) {
    const float* x     = (const float*)d_in[0];
    const float* in_w  = (const float*)d_in[1];
    const float* in_b  = (const float*)d_in[2];
    const float* out_w = (const float*)d_in[3];
    const float* out_b = (const float*)d_in[4];
    const float* ln1w  = (const float*)d_in[5];
    const float* ln1b  = (const float*)d_in[6];
    const float* ln2w  = (const float*)d_in[7];
    const float* ln2b  = (const float*)d_in[8];
    const float* w1    = (const float*)d_in[9];
    const float* b1    = (const float*)d_in[10];
    const float* w2    = (const float*)d_in[11];
    const float* b2    = (const float*)d_in[12];
    float* out = (float*)d_out;

    static bf16 *p_proj_h=nullptr, *p_proj_l, *p_ctx_h, *p_ctx_l,
                *p_x1h, *p_x1l, *p_hh, *p_hl, *p_wh, *p_wl;
    static float *p_qkv, *p_x1f, *p_t0;
    if (!p_proj_h) {
        cudaGetSymbolAddress((void**)&p_proj_h, g_proj_h);
        cudaGetSymbolAddress((void**)&p_proj_l, g_proj_l);
        cudaGetSymbolAddress((void**)&p_qkv,   g_qkv);
        cudaGetSymbolAddress((void**)&p_ctx_h, g_ctx_h);
        cudaGetSymbolAddress((void**)&p_ctx_l, g_ctx_l);
        cudaGetSymbolAddress((void**)&p_x1f,   g_x1f);
        cudaGetSymbolAddress((void**)&p_x1h,   g_x1_h);
        cudaGetSymbolAddress((void**)&p_x1l,   g_x1_l);
        cudaGetSymbolAddress((void**)&p_hh,    g_hh);
        cudaGetSymbolAddress((void**)&p_hl,    g_hl);
        cudaGetSymbolAddress((void**)&p_t0,    g_t0);
        cudaGetSymbolAddress((void**)&p_wh,    g_wh);
        cudaGetSymbolAddress((void**)&p_wl,    g_wl);
    }

    // weight splits
    split_kernel<<<(QKVN*EE/4 + 255)/256, 256>>>(in_w,  p_wh + W_INW,  p_wl + W_INW,  QKVN*EE/4);
    split_kernel<<<(EE*EE/4   + 255)/256, 256>>>(out_w, p_wh + W_OUTW, p_wl + W_OUTW, EE*EE/4);
    split_kernel<<<(FFNN*EE/4 + 255)/256, 256>>>(w1,    p_wh + W_W1,   p_wl + W_W1,   FFNN*EE/4);
    split_kernel<<<(EE*FFNN/4 + 255)/256, 256>>>(w2,    p_wh + W_W2,   p_wl + W_W2,   EE*FFNN/4);

    // proj (prefix-cos) with bf16 hi/lo split
    const int ngroups = MROWS * EE / 8;
    proj_kernel<<<(ngroups + 255)/256, 256>>>(x, p_proj_h, p_proj_l, ngroups);

    // qkv = proj @ in_w^T + in_b  (2048 x 1536, K=512) -> fp32
    gemm_mma<4,0,false><<<dim3(QKVN/128, MROWS/128), 256>>>(
        p_proj_h, p_proj_l, p_wh + W_INW, p_wl + W_INW, in_b,
        p_qkv, nullptr, nullptr, QKVN, EE);

    // attention -> ctx hi/lo
    attn_kernel<<<BBATCH * HH, SS>>>(p_qkv, p_ctx_h, p_ctx_l);

    // attn_out = ctx @ out_w^T + out_b (2048 x 512, K=512) -> t0 fp32 ; BM=64 grid=128
    gemm_mma<2,0,false><<<dim3(EE/128, MROWS/64), 256>>>(
        p_ctx_h, p_ctx_l, p_wh + W_OUTW, p_wl + W_OUTW, out_b,
        p_t0, nullptr, nullptr, EE, EE);

    // x1 = LN(x + attn_out) -> fp32 + hi/lo
    add_ln_kernel<true><<<MROWS, 128>>>(x, p_t0, ln1w, ln1b, p_x1f, p_x1h, p_x1l);

    // h = relu(x1 @ w1^T + b1) (2048 x 2048, K=512) -> hi/lo only
    gemm_mma<4,1,true><<<dim3(FFNN/128, MROWS/128), 256>>>(
        p_x1h, p_x1l, p_wh + W_W1, p_wl + W_W1, b1,
        nullptr, p_hh, p_hl, FFNN, EE);

    // ffn_out = h @ w2^T + b2 (2048 x 512, K=2048) -> t0 fp32 ; BM=64 grid=128
    gemm_mma<2,0,false><<<dim3(EE/128, MROWS/64), 256>>>(
        p_hh, p_hl, p_wh + W_W2, p_wl + W_W2, b2,
        p_t0, nullptr, nullptr, EE, FFNN);

    // out = LN(x1 + ffn_out)
    add_ln_kernel<false><<<MROWS, 128>>>(p_x1f, p_t0, ln2w, ln2b, out, nullptr, nullptr);

    (void)in_sizes; (void)n_in; (void)out_size;
}

// round 5
// speedup vs baseline: 2.2378x; 1.1021x over previous
#include <cuda_runtime.h>
#include <cuda_bf16.h>
#include <math.h>
#include <stdint.h>

#define BBATCH 4
#define SS 512
#define EE 512
#define HH 64
#define FFNN 2048
#define MROWS 2048
#define QKVN 1536

typedef __nv_bfloat16 bf16;
typedef __nv_bfloat162 bf162;

// ---------------- scratch (__device__ globals; no allocations allowed) ----------------
__device__ bf16  g_proj_h[MROWS*EE];
__device__ bf16  g_proj_l[MROWS*EE];
__device__ float g_qkv  [MROWS*QKVN];
__device__ bf16  g_ctx_h[MROWS*EE];
__device__ bf16  g_ctx_l[MROWS*EE];
__device__ float g_x1f  [MROWS*EE];
__device__ bf16  g_x1_h [MROWS*EE];
__device__ bf16  g_x1_l [MROWS*EE];
__device__ bf16  g_hh   [MROWS*FFNN];
__device__ bf16  g_hl   [MROWS*FFNN];
__device__ float g_t0   [MROWS*EE];
#define W_INW  0
#define W_OUTW (QKVN*EE)
#define W_W1   (W_OUTW + EE*EE)
#define W_W2   (W_W1 + FFNN*EE)
#define W_TOTAL (W_W2 + EE*FFNN)
__device__ bf16  g_wh[W_TOTAL];
__device__ bf16  g_wl[W_TOTAL];

// ---------------- helpers ----------------
__device__ __forceinline__ void split1(float v, bf16& h, bf16& l) {
    h = __float2bfloat16(v);
    l = __float2bfloat16(v - __bfloat162float(h));
}
__device__ __forceinline__ uint32_t smem_u32(const void* p) {
    return (uint32_t)__cvta_generic_to_shared(p);
}
__device__ __forceinline__ void ldm_x4(uint32_t* r, uint32_t addr) {
    asm volatile("ldmatrix.sync.aligned.m8n8.x4.shared.b16 {%0,%1,%2,%3}, [%4];"
                 : "=r"(r[0]), "=r"(r[1]), "=r"(r[2]), "=r"(r[3]) : "r"(addr));
}
__device__ __forceinline__ void mma16816(float* c, const uint32_t* a, const uint32_t* b) {
    asm volatile("mma.sync.aligned.m16n8k16.row.col.f32.bf16.bf16.f32 "
                 "{%0,%1,%2,%3},{%4,%5,%6,%7},{%8,%9},{%0,%1,%2,%3};"
                 : "+f"(c[0]), "+f"(c[1]), "+f"(c[2]), "+f"(c[3])
                 : "r"(a[0]), "r"(a[1]), "r"(a[2]), "r"(a[3]), "r"(b[0]), "r"(b[1]));
}
__device__ __forceinline__ void cpa16(uint32_t dst, const void* src) {
    asm volatile("cp.async.cg.shared.global [%0], [%1], 16;" :: "r"(dst), "l"(src));
}
__device__ __forceinline__ uint32_t pack2(bf16 a, bf16 b) {
    bf162 t{a, b};
    return *reinterpret_cast<uint32_t*>(&t);
}

// ---------------- combined weight split ----------------
__global__ __launch_bounds__(256) void split_all_kernel(
    const float* __restrict__ in_w, const float* __restrict__ out_w,
    const float* __restrict__ w1, const float* __restrict__ w2,
    bf16* __restrict__ h, bf16* __restrict__ l) {
    int i = blockIdx.x * blockDim.x + threadIdx.x;   // float4 index
    if (i >= W_TOTAL / 4) return;
    int e = i * 4;
    const float* src; int off;
    if      (e < W_OUTW) { src = in_w;  off = e; }
    else if (e < W_W1)   { src = out_w; off = e - W_OUTW; }
    else if (e < W_W2)   { src = w1;    off = e - W_W1; }
    else                 { src = w2;    off = e - W_W2; }
    float4 v = *(const float4*)(src + off);
    bf16 h0,h1,h2,h3,l0,l1,l2,l3;
    split1(v.x,h0,l0); split1(v.y,h1,l1); split1(v.z,h2,l2); split1(v.w,h3,l3);
    ((bf162*)h)[i*2+0] = bf162{h0,h1};
    ((bf162*)h)[i*2+1] = bf162{h2,h3};
    ((bf162*)l)[i*2+0] = bf162{l0,l1};
    ((bf162*)l)[i*2+1] = bf162{l2,l3};
}

// ---------------- quantum projection == prefix product of cos ----------------
__global__ __launch_bounds__(256) void proj_kernel(const float* __restrict__ x,
                                                   bf16* __restrict__ ph,
                                                   bf16* __restrict__ pl, int ngroups) {
    int g = blockIdx.x * blockDim.x + threadIdx.x;
    if (g >= ngroups) return;
    const float4* xp = (const float4*)(x + (size_t)g * 8);
    float4 a = xp[0], b = xp[1];
    float r[8];
    r[0] = cosf(a.x);
    r[1] = r[0] * cosf(a.y);
    r[2] = r[1] * cosf(a.z);
    r[3] = r[2] * cosf(a.w);
    r[4] = r[3] * cosf(b.x);
    r[5] = r[4] * cosf(b.y);
    r[6] = r[5] * cosf(b.z);
    r[7] = r[6] * cosf(b.w);
    bf16 h[8], l[8];
#pragma unroll
    for (int i = 0; i < 8; i++) split1(r[i], h[i], l[i]);
    bf162* oh = (bf162*)(ph + (size_t)g * 8);
    bf162* ol = (bf162*)(pl + (size_t)g * 8);
#pragma unroll
    for (int i = 0; i < 4; i++) { oh[i] = bf162{h[2*i],h[2*i+1]}; ol[i] = bf162{l[2*i],l[2*i+1]}; }
}

// ---------------- 3xBF16 mma.sync GEMM: C = A(MxK) @ B(NxK)^T + bias ----------------
// BM = MFRAG*32 (128 or 64), BN = 128, BK = 32, 3-stage cp.async pipeline.
// 256 threads = 8 warps (2 M x 4 N), warp tile (MFRAG*16) x 32.
// EPI: 0 -> fp32 out; 1 -> bf16 hi/lo split out. RELU before epilogue write.
template<int MFRAG, int EPI, bool RELU>
__global__ __launch_bounds__(256) void gemm_mma(
    const bf16* __restrict__ Ah, const bf16* __restrict__ Al,
    const bf16* __restrict__ Bh, const bf16* __restrict__ Bl,
    const float* __restrict__ bias,
    float* __restrict__ Cf, bf16* __restrict__ Ch, bf16* __restrict__ Cl,
    int N, int K)
{
    constexpr int BM = MFRAG * 32;
    constexpr int ROWB = 80;                 // padded row bytes (40 bf16): conflict-free
    constexpr int A_SZ = BM * ROWB;
    constexpr int B_SZ = 128 * ROWB;
    constexpr int STAGE = 2 * A_SZ + 2 * B_SZ;

    extern __shared__ char dynsmem[];
    const uint32_t dbase = smem_u32(dynsmem);

    const int tid = threadIdx.x;
    const int lane = tid & 31, wid = tid >> 5;
    const int warp_m = wid >> 2, warp_n = wid & 3;
    const int m_base = warp_m * (MFRAG * 16);
    const int n_base = warp_n * 32;
    const int blockRow = blockIdx.y * BM;
    const int blockCol = blockIdx.x * 128;

    // ldmatrix per-lane row/col components (validated layout from R2)
    const int lg = lane >> 3, li = lane & 7;
    const int a_row = li + (lg & 1) * 8;
    const int a_col = (lg >> 1) * 8;
    const int b_row = li + (lg >> 1) * 8;
    const int b_col = (lg & 1) * 8;

    float acc[MFRAG][4][4];
#pragma unroll
    for (int mf = 0; mf < MFRAG; mf++)
#pragma unroll
        for (int nf = 0; nf < 4; nf++)
#pragma unroll
            for (int q = 0; q < 4; q++) acc[mf][nf][q] = 0.f;

    auto ld_arr = [&](const bf16* g, int row0, int k0, uint32_t sb, int rows) {
        const int nch = rows * 4;                    // 16B chunks (BK=32 -> 64B/row)
        for (int c = tid; c < nch; c += 256) {
            int r = c >> 2, seg = c & 3;
            cpa16(sb + (uint32_t)(r * ROWB + seg * 16),
                  g + (size_t)(row0 + r) * K + k0 + seg * 8);
        }
    };
    auto load_chunk = [&](int s, int kt) {
        const uint32_t sb = dbase + (uint32_t)s * STAGE;
        const int k0 = kt * 32;
        ld_arr(Ah, blockRow, k0, sb, BM);
        ld_arr(Al, blockRow, k0, sb + A_SZ, BM);
        ld_arr(Bh, blockCol, k0, sb + 2 * A_SZ, 128);
        ld_arr(Bl, blockCol, k0, sb + 2 * A_SZ + B_SZ, 128);
        asm volatile("cp.async.commit_group;");
    };

    const int T = K / 32;                            // >= 16 always
    load_chunk(0, 0);
    load_chunk(1, 1);
    load_chunk(2, 2);

    for (int it = 0; it < T; ++it) {
        if (it < T - 2)       asm volatile("cp.async.wait_group 2;");
        else if (it == T - 2) asm volatile("cp.async.wait_group 1;");
        else                  asm volatile("cp.async.wait_group 0;");
        __syncthreads();

        const int s = it % 3;
        const uint32_t aH = dbase + (uint32_t)s * STAGE;
        const uint32_t aL = aH + A_SZ;
        const uint32_t bH = aH + 2 * A_SZ;
        const uint32_t bL = bH + B_SZ;

        // load ALL fragments for both k16 substeps up-front (big ILP window)
        uint32_t fah[2][MFRAG][4], fal[2][MFRAG][4], fbh[2][2][4], fbl[2][2][4];
#pragma unroll
        for (int j = 0; j < 2; j++) {
#pragma unroll
            for (int mf = 0; mf < MFRAG; mf++) {
                uint32_t ro = (uint32_t)((m_base + mf * 16 + a_row) * ROWB
                                         + (j * 16 + a_col) * 2);
                ldm_x4(fah[j][mf], aH + ro);
                ldm_x4(fal[j][mf], aL + ro);
            }
#pragma unroll
            for (int nt = 0; nt < 2; nt++) {
                uint32_t ro = (uint32_t)((n_base + nt * 16 + b_row) * ROWB
                                         + (j * 16 + b_col) * 2);
                ldm_x4(fbh[j][nt], bH + ro);
                ldm_x4(fbl[j][nt], bL + ro);
            }
        }
#pragma unroll
        for (int j = 0; j < 2; j++) {
#pragma unroll
            for (int mf = 0; mf < MFRAG; mf++) {
#pragma unroll
                for (int nt = 0; nt < 2; nt++) {
#pragma unroll
                    for (int h = 0; h < 2; h++) {
                        const int nf = nt * 2 + h;
                        uint32_t bh2[2] = { fbh[j][nt][2*h], fbh[j][nt][2*h+1] };
                        uint32_t bl2[2] = { fbl[j][nt][2*h], fbl[j][nt][2*h+1] };
                        mma16816(acc[mf][nf], fah[j][mf], bh2);   // hi*hi
                        mma16816(acc[mf][nf], fah[j][mf], bl2);   // hi*lo
                        mma16816(acc[mf][nf], fal[j][mf], bh2);   // lo*hi
                    }
                }
            }
        }

        if (it + 3 < T) {
            __syncthreads();                         // buffer (it%3) free to refill
            load_chunk((it + 3) % 3, it + 3);
        }
    }

    // epilogue
#pragma unroll
    for (int mf = 0; mf < MFRAG; mf++) {
        const int r0 = blockRow + m_base + mf * 16 + (lane >> 2);
#pragma unroll
        for (int nf = 0; nf < 4; nf++) {
            const int col = blockCol + n_base + nf * 8 + ((lane & 3) << 1);
            const float2 bv = *(const float2*)(bias + col);
            float v0 = acc[mf][nf][0] + bv.x;
            float v1 = acc[mf][nf][1] + bv.y;
            float v2 = acc[mf][nf][2] + bv.x;
            float v3 = acc[mf][nf][3] + bv.y;
            if (RELU) {
                v0 = fmaxf(v0, 0.f); v1 = fmaxf(v1, 0.f);
                v2 = fmaxf(v2, 0.f); v3 = fmaxf(v3, 0.f);
            }
            if (EPI == 0) {
                *(float2*)(Cf + (size_t)r0 * N + col)       = make_float2(v0, v1);
                *(float2*)(Cf + (size_t)(r0 + 8) * N + col) = make_float2(v2, v3);
            } else {
                bf16 h0,h1,h2,h3,l0,l1,l2,l3;
                split1(v0,h0,l0); split1(v1,h1,l1); split1(v2,h2,l2); split1(v3,h3,l3);
                *(bf162*)(Ch + (size_t)r0 * N + col)       = bf162{h0,h1};
                *(bf162*)(Ch + (size_t)(r0 + 8) * N + col) = bf162{h2,h3};
                *(bf162*)(Cl + (size_t)r0 * N + col)       = bf162{l0,l1};
                *(bf162*)(Cl + (size_t)(r0 + 8) * N + col) = bf162{l2,l3};
            }
        }
    }
}

// ---------------- attention: one block per (b,h), one thread per query row ----------------
__global__ __launch_bounds__(512) void attn_kernel(const float* __restrict__ qkv,
                                                   bf16* __restrict__ ch,
                                                   bf16* __restrict__ cl) {
    const int bh = blockIdx.x;
    const int b = bh / HH, h = bh % HH;
    __shared__ float Ks[SS][8];
    __shared__ float Vs[SS][8];
    const int t = threadIdx.x;
    const float* base = qkv + (size_t)b * SS * QKVN;
    {
        const float* kr = base + (size_t)t * QKVN + EE     + h * 8;
        const float* vr = base + (size_t)t * QKVN + 2 * EE + h * 8;
        float4 k0 = *(const float4*)kr, k1 = *(const float4*)(kr + 4);
        float4 v0 = *(const float4*)vr, v1 = *(const float4*)(vr + 4);
        Ks[t][0]=k0.x; Ks[t][1]=k0.y; Ks[t][2]=k0.z; Ks[t][3]=k0.w;
        Ks[t][4]=k1.x; Ks[t][5]=k1.y; Ks[t][6]=k1.z; Ks[t][7]=k1.w;
        Vs[t][0]=v0.x; Vs[t][1]=v0.y; Vs[t][2]=v0.z; Vs[t][3]=v0.w;
        Vs[t][4]=v1.x; Vs[t][5]=v1.y; Vs[t][6]=v1.z; Vs[t][7]=v1.w;
    }
    __syncthreads();
    float q[8];
    {
        const float* qr = base + (size_t)t * QKVN + h * 8;
        float4 q0 = *(const float4*)qr, q1 = *(const float4*)(qr + 4);
        q[0]=q0.x; q[1]=q0.y; q[2]=q0.z; q[3]=q0.w;
        q[4]=q1.x; q[5]=q1.y; q[6]=q1.z; q[7]=q1.w;
    }
    const float sc = 0.35355339059327373f;
    float m = -1e30f, l = 0.f;
    float acc[8] = {0,0,0,0,0,0,0,0};
    for (int j = 0; j < SS; j++) {
        float s = 0.f;
#pragma unroll
        for (int d = 0; d < 8; d++) s += q[d] * Ks[j][d];
        s *= sc;
        float nm = fmaxf(m, s);
        float c  = __expf(m - nm);
        float p  = __expf(s - nm);
        l = l * c + p;
#pragma unroll
        for (int d = 0; d < 8; d++) acc[d] = acc[d] * c + p * Vs[j][d];
        m = nm;
    }
    const float inv = 1.f / l;
    const size_t o = (size_t)(b * SS + t) * EE + h * 8;
    bf16 oh[8], ol[8];
#pragma unroll
    for (int d = 0; d < 8; d++) split1(acc[d] * inv, oh[d], ol[d]);
#pragma unroll
    for (int i = 0; i < 4; i++) {
        *(bf162*)(ch + o + 2*i) = bf162{oh[2*i], oh[2*i+1]};
        *(bf162*)(cl + o + 2*i) = bf162{ol[2*i], ol[2*i+1]};
    }
}

// ---------------- fused residual add + layernorm over E=512 ----------------
template<bool SPLIT>
__global__ __launch_bounds__(128) void add_ln_kernel(const float* __restrict__ a,
                                                     const float* __restrict__ r,
                                                     const float* __restrict__ w,
                                                     const float* __restrict__ bb,
                                                     float* __restrict__ out,
                                                     bf16* __restrict__ oh,
                                                     bf16* __restrict__ ol) {
    const int row = blockIdx.x;
    const int t = threadIdx.x;
    const float4 av = ((const float4*)(a + (size_t)row * EE))[t];
    const float4 rv = ((const float4*)(r + (size_t)row * EE))[t];
    float v0 = av.x + rv.x, v1 = av.y + rv.y, v2 = av.z + rv.z, v3 = av.w + rv.w;

    __shared__ float sh[4];
    __shared__ float sh2[4];
    float s = v0 + v1 + v2 + v3;
#pragma unroll
    for (int o = 16; o; o >>= 1) s += __shfl_xor_sync(0xffffffffu, s, o);
    if ((t & 31) == 0) sh[t >> 5] = s;
    __syncthreads();
    const float mean = (sh[0] + sh[1] + sh[2] + sh[3]) * (1.f / 512.f);

    float d0 = v0 - mean, d1 = v1 - mean, d2 = v2 - mean, d3 = v3 - mean;
    float qsum = d0*d0 + d1*d1 + d2*d2 + d3*d3;
#pragma unroll
    for (int o = 16; o; o >>= 1) qsum += __shfl_xor_sync(0xffffffffu, qsum, o);
    if ((t & 31) == 0) sh2[t >> 5] = qsum;
    __syncthreads();
    const float var = (sh2[0] + sh2[1] + sh2[2] + sh2[3]) * (1.f / 512.f);
    const float inv = rsqrtf(var + 1e-5f);

    const float4 wv = ((const float4*)w)[t];
    const float4 bv = ((const float4*)bb)[t];
    float o0 = d0 * inv * wv.x + bv.x;
    float o1 = d1 * inv * wv.y + bv.y;
    float o2 = d2 * inv * wv.z + bv.z;
    float o3 = d3 * inv * wv.w + bv.w;
    ((float4*)(out + (size_t)row * EE))[t] = make_float4(o0, o1, o2, o3);
    if (SPLIT) {
        bf16 h0,h1,h2,h3,l0,l1,l2,l3;
        split1(o0,h0,l0); split1(o1,h1,l1); split1(o2,h2,l2); split1(o3,h3,l3);
        bf162* ph = (bf162*)(oh + (size_t)row * EE + t * 4);
        bf162* pl = (bf162*)(ol + (size_t)row * EE + t * 4);
        ph[0] = bf162{h0,h1}; ph[1] = bf162{h2,h3};
        pl[0] = bf162{l0,l1}; pl[1] = bf162{l2,l3};
    }
}

// ---------------- host launch ----------------
#define SMEMB(MFRAG) (3 * (2 * ((MFRAG)*32*80) + 2 * (128*80)))

extern "C" void kernel_launch(void* const* d_in, const int* in_sizes, int n_in,
                              void* d_out, int out_size) {
    const float* x     = (const float*)d_in[0];
    const float* in_w  = (const float*)d_in[1];
    const float* in_b  = (const float*)d_in[2];
    const float* out_w = (const float*)d_in[3];
    const float* out_b = (const float*)d_in[4];
    const float* ln1w  = (const float*)d_in[5];
    const float* ln1b  = (const float*)d_in[6];
    const float* ln2w  = (const float*)d_in[7];
    const float* ln2b  = (const float*)d_in[8];
    const float* w1    = (const float*)d_in[9];
    const float* b1    = (const float*)d_in[10];
    const float* w2    = (const float*)d_in[11];
    const float* b2    = (const float*)d_in[12];
    float* out = (float*)d_out;

    static bf16 *p_proj_h=nullptr, *p_proj_l, *p_ctx_h, *p_ctx_l,
                *p_x1h, *p_x1l, *p_hh, *p_hl, *p_wh, *p_wl;
    static float *p_qkv, *p_x1f, *p_t0;
    if (!p_proj_h) {
        cudaGetSymbolAddress((void**)&p_proj_h, g_proj_h);
        cudaGetSymbolAddress((void**)&p_proj_l, g_proj_l);
        cudaGetSymbolAddress((void**)&p_qkv,   g_qkv);
        cudaGetSymbolAddress((void**)&p_ctx_h, g_ctx_h);
        cudaGetSymbolAddress((void**)&p_ctx_l, g_ctx_l);
        cudaGetSymbolAddress((void**)&p_x1f,   g_x1f);
        cudaGetSymbolAddress((void**)&p_x1h,   g_x1_h);
        cudaGetSymbolAddress((void**)&p_x1l,   g_x1_l);
        cudaGetSymbolAddress((void**)&p_hh,    g_hh);
        cudaGetSymbolAddress((void**)&p_hl,    g_hl);
        cudaGetSymbolAddress((void**)&p_t0,    g_t0);
        cudaGetSymbolAddress((void**)&p_wh,    g_wh);
        cudaGetSymbolAddress((void**)&p_wl,    g_wl);
        cudaFuncSetAttribute(gemm_mma<4,0,false>, cudaFuncAttributeMaxDynamicSharedMemorySize, SMEMB(4));
        cudaFuncSetAttribute(gemm_mma<4,1,true >, cudaFuncAttributeMaxDynamicSharedMemorySize, SMEMB(4));
        cudaFuncSetAttribute(gemm_mma<2,0,false>, cudaFuncAttributeMaxDynamicSharedMemorySize, SMEMB(2));
    }

    // weight splits (one kernel)
    split_all_kernel<<<(W_TOTAL/4 + 255)/256, 256>>>(in_w, out_w, w1, w2, p_wh, p_wl);

    // proj (prefix-cos) with bf16 hi/lo split
    const int ngroups = MROWS * EE / 8;
    proj_kernel<<<(ngroups + 255)/256, 256>>>(x, p_proj_h, p_proj_l, ngroups);

    // qkv = proj @ in_w^T + in_b  (2048 x 1536, K=512) -> fp32
    gemm_mma<4,0,false><<<dim3(QKVN/128, MROWS/128), 256, SMEMB(4)>>>(
        p_proj_h, p_proj_l, p_wh + W_INW, p_wl + W_INW, in_b,
        p_qkv, nullptr, nullptr, QKVN, EE);

    // attention -> ctx hi/lo
    attn_kernel<<<BBATCH * HH, SS>>>(p_qkv, p_ctx_h, p_ctx_l);

    // attn_out = ctx @ out_w^T + out_b (2048 x 512, K=512) -> t0 fp32 ; BM=64 grid=128
    gemm_mma<2,0,false><<<dim3(EE/128, MROWS/64), 256, SMEMB(2)>>>(
        p_ctx_h, p_ctx_l, p_wh + W_OUTW, p_wl + W_OUTW, out_b,
        p_t0, nullptr, nullptr, EE, EE);

    // x1 = LN(x + attn_out) -> fp32 + hi/lo
    add_ln_kernel<true><<<MROWS, 128>>>(x, p_t0, ln1w, ln1b, p_x1f, p_x1h, p_x1l);

    // h = relu(x1 @ w1^T + b1) (2048 x 2048, K=512) -> hi/lo only
    gemm_mma<4,1,true><<<dim3(FFNN/128, MROWS/128), 256, SMEMB(4)>>>(
        p_x1h, p_x1l, p_wh + W_W1, p_wl + W_W1, b1,
        nullptr, p_hh, p_hl, FFNN, EE);

    // ffn_out = h @ w2^T + b2 (2048 x 512, K=2048) -> t0 fp32 ; BM=64 grid=128
    gemm_mma<2,0,false><<<dim3(EE/128, MROWS/64), 256, SMEMB(2)>>>(
        p_hh, p_hl, p_wh + W_W2, p_wl + W_W2, b2,
        p_t0, nullptr, nullptr, EE, FFNN);

    // out = LN(x1 + ffn_out)
    add_ln_kernel<false><<<MROWS, 128>>>(p_x1f, p_t0, ln2w, ln2b, out, nullptr, nullptr);

    (void)in_sizes; (void)n_in; (void)out_size;
}

// round 8
// speedup vs baseline: 2.5180x; 1.1252x over previous
#include <cuda_runtime.h>
#include <cuda_bf16.h>
#include <math.h>
#include <stdint.h>

#define BBATCH 4
#define SS 512
#define EE 512
#define HH 64
#define FFNN 2048
#define MROWS 2048
#define QKVN 1536

typedef __nv_bfloat16 bf16;
typedef __nv_bfloat162 bf162;

// ---------------- scratch (__device__ globals; no allocations allowed) ----------------
__device__ bf16  g_proj_h[MROWS*EE];
__device__ bf16  g_proj_l[MROWS*EE];
__device__ float g_qkv  [MROWS*QKVN];
__device__ bf16  g_ctx_h[MROWS*EE];
__device__ bf16  g_ctx_l[MROWS*EE];
__device__ float g_x1f  [MROWS*EE];
__device__ bf16  g_x1_h [MROWS*EE];
__device__ bf16  g_x1_l [MROWS*EE];
__device__ bf16  g_hh   [MROWS*FFNN];
__device__ bf16  g_hl   [MROWS*FFNN];
__device__ float g_t0   [MROWS*EE];
#define W_INW  0
#define W_OUTW (QKVN*EE)
#define W_W1   (W_OUTW + EE*EE)
#define W_W2   (W_W1 + FFNN*EE)
#define W_TOTAL (W_W2 + EE*FFNN)
__device__ bf16  g_wh[W_TOTAL];
__device__ bf16  g_wl[W_TOTAL];

// ---------------- helpers ----------------
__device__ __forceinline__ void split1(float v, bf16& h, bf16& l) {
    h = __float2bfloat16(v);
    l = __float2bfloat16(v - __bfloat162float(h));
}
__device__ __forceinline__ uint32_t smem_u32(const void* p) {
    return (uint32_t)__cvta_generic_to_shared(p);
}
__device__ __forceinline__ void ldm_x4(uint32_t* r, uint32_t addr) {
    asm volatile("ldmatrix.sync.aligned.m8n8.x4.shared.b16 {%0,%1,%2,%3}, [%4];"
                 : "=r"(r[0]), "=r"(r[1]), "=r"(r[2]), "=r"(r[3]) : "r"(addr));
}
__device__ __forceinline__ void mma16816(float* c, const uint32_t* a, const uint32_t* b) {
    asm volatile("mma.sync.aligned.m16n8k16.row.col.f32.bf16.bf16.f32 "
                 "{%0,%1,%2,%3},{%4,%5,%6,%7},{%8,%9},{%0,%1,%2,%3};"
                 : "+f"(c[0]), "+f"(c[1]), "+f"(c[2]), "+f"(c[3])
                 : "r"(a[0]), "r"(a[1]), "r"(a[2]), "r"(a[3]), "r"(b[0]), "r"(b[1]));
}
__device__ __forceinline__ void cpa16(uint32_t dst, const void* src) {
    asm volatile("cp.async.cg.shared.global [%0], [%1], 16;" :: "r"(dst), "l"(src));
}
__device__ __forceinline__ uint32_t pack2(bf16 a, bf16 b) {
    bf162 t{a, b};
    return *reinterpret_cast<uint32_t*>(&t);
}

// ---------------- combined weight split ----------------
__global__ __launch_bounds__(256) void split_all_kernel(
    const float* __restrict__ in_w, const float* __restrict__ out_w,
    const float* __restrict__ w1, const float* __restrict__ w2,
    bf16* __restrict__ h, bf16* __restrict__ l) {
    int i = blockIdx.x * blockDim.x + threadIdx.x;   // float4 index
    if (i >= W_TOTAL / 4) return;
    int e = i * 4;
    const float* src; int off;
    if      (e < W_OUTW) { src = in_w;  off = e; }
    else if (e < W_W1)   { src = out_w; off = e - W_OUTW; }
    else if (e < W_W2)   { src = w1;    off = e - W_W1; }
    else                 { src = w2;    off = e - W_W2; }
    float4 v = *(const float4*)(src + off);
    bf16 h0,h1,h2,h3,l0,l1,l2,l3;
    split1(v.x,h0,l0); split1(v.y,h1,l1); split1(v.z,h2,l2); split1(v.w,h3,l3);
    ((bf162*)h)[i*2+0] = bf162{h0,h1};
    ((bf162*)h)[i*2+1] = bf162{h2,h3};
    ((bf162*)l)[i*2+0] = bf162{l0,l1};
    ((bf162*)l)[i*2+1] = bf162{l2,l3};
}

// ---------------- quantum projection == prefix product of cos ----------------
__global__ __launch_bounds__(256) void proj_kernel(const float* __restrict__ x,
                                                   bf16* __restrict__ ph,
                                                   bf16* __restrict__ pl, int ngroups) {
    int g = blockIdx.x * blockDim.x + threadIdx.x;
    if (g >= ngroups) return;
    const float4* xp = (const float4*)(x + (size_t)g * 8);
    float4 a = xp[0], b = xp[1];
    float r[8];
    r[0] = cosf(a.x);
    r[1] = r[0] * cosf(a.y);
    r[2] = r[1] * cosf(a.z);
    r[3] = r[2] * cosf(a.w);
    r[4] = r[3] * cosf(b.x);
    r[5] = r[4] * cosf(b.y);
    r[6] = r[5] * cosf(b.z);
    r[7] = r[6] * cosf(b.w);
    bf16 h[8], l[8];
#pragma unroll
    for (int i = 0; i < 8; i++) split1(r[i], h[i], l[i]);
    bf162* oh = (bf162*)(ph + (size_t)g * 8);
    bf162* ol = (bf162*)(pl + (size_t)g * 8);
#pragma unroll
    for (int i = 0; i < 4; i++) { oh[i] = bf162{h[2*i],h[2*i+1]}; ol[i] = bf162{l[2*i],l[2*i+1]}; }
}

// ---------------- 3xBF16 mma.sync GEMM: C = A(MxK) @ B(NxK)^T + bias ----------------
template<int MFRAG, int EPI, bool RELU>
__global__ __launch_bounds__(256) void gemm_mma(
    const bf16* __restrict__ Ah, const bf16* __restrict__ Al,
    const bf16* __restrict__ Bh, const bf16* __restrict__ Bl,
    const float* __restrict__ bias,
    float* __restrict__ Cf, bf16* __restrict__ Ch, bf16* __restrict__ Cl,
    int N, int K)
{
    constexpr int BM = MFRAG * 32;
    constexpr int ROWB = 80;
    constexpr int A_SZ = BM * ROWB;
    constexpr int B_SZ = 128 * ROWB;
    constexpr int STAGE = 2 * A_SZ + 2 * B_SZ;

    extern __shared__ char dynsmem[];
    const uint32_t dbase = smem_u32(dynsmem);

    const int tid = threadIdx.x;
    const int lane = tid & 31, wid = tid >> 5;
    const int warp_m = wid >> 2, warp_n = wid & 3;
    const int m_base = warp_m * (MFRAG * 16);
    const int n_base = warp_n * 32;
    const int blockRow = blockIdx.y * BM;
    const int blockCol = blockIdx.x * 128;

    const int lg = lane >> 3, li = lane & 7;
    const int a_row = li + (lg & 1) * 8;
    const int a_col = (lg >> 1) * 8;
    const int b_row = li + (lg >> 1) * 8;
    const int b_col = (lg & 1) * 8;

    float acc[MFRAG][4][4];
#pragma unroll
    for (int mf = 0; mf < MFRAG; mf++)
#pragma unroll
        for (int nf = 0; nf < 4; nf++)
#pragma unroll
            for (int q = 0; q < 4; q++) acc[mf][nf][q] = 0.f;

    auto ld_arr = [&](const bf16* g, int row0, int k0, uint32_t sb, int rows) {
        const int nch = rows * 4;
        for (int c = tid; c < nch; c += 256) {
            int r = c >> 2, seg = c & 3;
            cpa16(sb + (uint32_t)(r * ROWB + seg * 16),
                  g + (size_t)(row0 + r) * K + k0 + seg * 8);
        }
    };
    auto load_chunk = [&](int s, int kt) {
        const uint32_t sb = dbase + (uint32_t)s * STAGE;
        const int k0 = kt * 32;
        ld_arr(Ah, blockRow, k0, sb, BM);
        ld_arr(Al, blockRow, k0, sb + A_SZ, BM);
        ld_arr(Bh, blockCol, k0, sb + 2 * A_SZ, 128);
        ld_arr(Bl, blockCol, k0, sb + 2 * A_SZ + B_SZ, 128);
        asm volatile("cp.async.commit_group;");
    };

    const int T = K / 32;
    load_chunk(0, 0);
    load_chunk(1, 1);
    load_chunk(2, 2);

    for (int it = 0; it < T; ++it) {
        if (it < T - 2)       asm volatile("cp.async.wait_group 2;");
        else if (it == T - 2) asm volatile("cp.async.wait_group 1;");
        else                  asm volatile("cp.async.wait_group 0;");
        __syncthreads();

        const int s = it % 3;
        const uint32_t aH = dbase + (uint32_t)s * STAGE;
        const uint32_t aL = aH + A_SZ;
        const uint32_t bH = aH + 2 * A_SZ;
        const uint32_t bL = bH + B_SZ;

        uint32_t fah[2][MFRAG][4], fal[2][MFRAG][4], fbh[2][2][4], fbl[2][2][4];
#pragma unroll
        for (int j = 0; j < 2; j++) {
#pragma unroll
            for (int mf = 0; mf < MFRAG; mf++) {
                uint32_t ro = (uint32_t)((m_base + mf * 16 + a_row) * ROWB
                                         + (j * 16 + a_col) * 2);
                ldm_x4(fah[j][mf], aH + ro);
                ldm_x4(fal[j][mf], aL + ro);
            }
#pragma unroll
            for (int nt = 0; nt < 2; nt++) {
                uint32_t ro = (uint32_t)((n_base + nt * 16 + b_row) * ROWB
                                         + (j * 16 + b_col) * 2);
                ldm_x4(fbh[j][nt], bH + ro);
                ldm_x4(fbl[j][nt], bL + ro);
            }
        }
#pragma unroll
        for (int j = 0; j < 2; j++) {
#pragma unroll
            for (int mf = 0; mf < MFRAG; mf++) {
#pragma unroll
                for (int nt = 0; nt < 2; nt++) {
#pragma unroll
                    for (int h = 0; h < 2; h++) {
                        const int nf = nt * 2 + h;
                        uint32_t bh2[2] = { fbh[j][nt][2*h], fbh[j][nt][2*h+1] };
                        uint32_t bl2[2] = { fbl[j][nt][2*h], fbl[j][nt][2*h+1] };
                        mma16816(acc[mf][nf], fah[j][mf], bh2);
                        mma16816(acc[mf][nf], fah[j][mf], bl2);
                        mma16816(acc[mf][nf], fal[j][mf], bh2);
                    }
                }
            }
        }

        if (it + 3 < T) {
            __syncthreads();
            load_chunk((it + 3) % 3, it + 3);
        }
    }

#pragma unroll
    for (int mf = 0; mf < MFRAG; mf++) {
        const int r0 = blockRow + m_base + mf * 16 + (lane >> 2);
#pragma unroll
        for (int nf = 0; nf < 4; nf++) {
            const int col = blockCol + n_base + nf * 8 + ((lane & 3) << 1);
            const float2 bv = *(const float2*)(bias + col);
            float v0 = acc[mf][nf][0] + bv.x;
            float v1 = acc[mf][nf][1] + bv.y;
            float v2 = acc[mf][nf][2] + bv.x;
            float v3 = acc[mf][nf][3] + bv.y;
            if (RELU) {
                v0 = fmaxf(v0, 0.f); v1 = fmaxf(v1, 0.f);
                v2 = fmaxf(v2, 0.f); v3 = fmaxf(v3, 0.f);
            }
            if (EPI == 0) {
                *(float2*)(Cf + (size_t)r0 * N + col)       = make_float2(v0, v1);
                *(float2*)(Cf + (size_t)(r0 + 8) * N + col) = make_float2(v2, v3);
            } else {
                bf16 h0,h1,h2,h3,l0,l1,l2,l3;
                split1(v0,h0,l0); split1(v1,h1,l1); split1(v2,h2,l2); split1(v3,h3,l3);
                *(bf162*)(Ch + (size_t)r0 * N + col)       = bf162{h0,h1};
                *(bf162*)(Ch + (size_t)(r0 + 8) * N + col) = bf162{h2,h3};
                *(bf162*)(Cl + (size_t)r0 * N + col)       = bf162{l0,l1};
                *(bf162*)(Cl + (size_t)(r0 + 8) * N + col) = bf162{l2,l3};
            }
        }
    }
}

// ---------------- attention: direct-exp softmax (scores bounded), float4 LDS ----------------
__global__ __launch_bounds__(512) void attn_kernel(const float* __restrict__ qkv,
                                                   bf16* __restrict__ ch,
                                                   bf16* __restrict__ cl) {
    const int bh = blockIdx.x;
    const int b = bh / HH, h = bh % HH;
    __shared__ float4 Ks[SS][2];
    __shared__ float4 Vs[SS][2];
    const int t = threadIdx.x;
    const float* base = qkv + (size_t)b * SS * QKVN;
    {
        const float* kr = base + (size_t)t * QKVN + EE     + h * 8;
        const float* vr = base + (size_t)t * QKVN + 2 * EE + h * 8;
        Ks[t][0] = *(const float4*)kr;     Ks[t][1] = *(const float4*)(kr + 4);
        Vs[t][0] = *(const float4*)vr;     Vs[t][1] = *(const float4*)(vr + 4);
    }
    __syncthreads();

    const float sc = 0.35355339059327373f;   // 1/sqrt(8)
    float4 q0, q1;
    {
        const float* qr = base + (size_t)t * QKVN + h * 8;
        q0 = *(const float4*)qr; q1 = *(const float4*)(qr + 4);
        q0.x *= sc; q0.y *= sc; q0.z *= sc; q0.w *= sc;
        q1.x *= sc; q1.y *= sc; q1.z *= sc; q1.w *= sc;
    }

    float l = 0.f;
    float a0 = 0.f, a1 = 0.f, a2 = 0.f, a3 = 0.f;
    float a4 = 0.f, a5 = 0.f, a6 = 0.f, a7 = 0.f;
    for (int j = 0; j < SS; j++) {
        const float4 k0 = Ks[j][0], k1 = Ks[j][1];
        float s = q0.x * k0.x + q0.y * k0.y + q0.z * k0.z + q0.w * k0.w
                + q1.x * k1.x + q1.y * k1.y + q1.z * k1.z + q1.w * k1.w;
        const float p = __expf(s);          // scores bounded; no max-shift needed
        l += p;
        const float4 v0 = Vs[j][0], v1 = Vs[j][1];
        a0 += p * v0.x; a1 += p * v0.y; a2 += p * v0.z; a3 += p * v0.w;
        a4 += p * v1.x; a5 += p * v1.y; a6 += p * v1.z; a7 += p * v1.w;
    }
    const float inv = 1.f / l;
    const size_t o = (size_t)(b * SS + t) * EE + h * 8;
    float r[8] = { a0*inv, a1*inv, a2*inv, a3*inv, a4*inv, a5*inv, a6*inv, a7*inv };
    bf16 oh[8], ol[8];
#pragma unroll
    for (int d = 0; d < 8; d++) split1(r[d], oh[d], ol[d]);
    uint4 uh, ul;
    uh.x = pack2(oh[0],oh[1]); uh.y = pack2(oh[2],oh[3]);
    uh.z = pack2(oh[4],oh[5]); uh.w = pack2(oh[6],oh[7]);
    ul.x = pack2(ol[0],ol[1]); ul.y = pack2(ol[2],ol[3]);
    ul.z = pack2(ol[4],ol[5]); ul.w = pack2(ol[6],ol[7]);
    *(uint4*)(ch + o) = uh;
    *(uint4*)(cl + o) = ul;
}

// ---------------- fused residual add + layernorm over E=512 ----------------
template<bool SPLIT>
__global__ __launch_bounds__(128) void add_ln_kernel(const float* __restrict__ a,
                                                     const float* __restrict__ r,
                                                     const float* __restrict__ w,
                                                     const float* __restrict__ bb,
                                                     float* __restrict__ out,
                                                     bf16* __restrict__ oh,
                                                     bf16* __restrict__ ol) {
    const int row = blockIdx.x;
    const int t = threadIdx.x;
    const float4 av = ((const float4*)(a + (size_t)row * EE))[t];
    const float4 rv = ((const float4*)(r + (size_t)row * EE))[t];
    float v0 = av.x + rv.x, v1 = av.y + rv.y, v2 = av.z + rv.z, v3 = av.w + rv.w;

    __shared__ float sh[4];
    __shared__ float sh2[4];
    float s = v0 + v1 + v2 + v3;
#pragma unroll
    for (int o = 16; o; o >>= 1) s += __shfl_xor_sync(0xffffffffu, s, o);
    if ((t & 31) == 0) sh[t >> 5] = s;
    __syncthreads();
    const float mean = (sh[0] + sh[1] + sh[2] + sh[3]) * (1.f / 512.f);

    float d0 = v0 - mean, d1 = v1 - mean, d2 = v2 - mean, d3 = v3 - mean;
    float qsum = d0*d0 + d1*d1 + d2*d2 + d3*d3;
#pragma unroll
    for (int o = 16; o; o >>= 1) qsum += __shfl_xor_sync(0xffffffffu, qsum, o);
    if ((t & 31) == 0) sh2[t >> 5] = qsum;
    __syncthreads();
    const float var = (sh2[0] + sh2[1] + sh2[2] + sh2[3]) * (1.f / 512.f);
    const float inv = rsqrtf(var + 1e-5f);

    const float4 wv = ((const float4*)w)[t];
    const float4 bv = ((const float4*)bb)[t];
    float o0 = d0 * inv * wv.x + bv.x;
    float o1 = d1 * inv * wv.y + bv.y;
    float o2 = d2 * inv * wv.z + bv.z;
    float o3 = d3 * inv * wv.w + bv.w;
    ((float4*)(out + (size_t)row * EE))[t] = make_float4(o0, o1, o2, o3);
    if (SPLIT) {
        bf16 h0,h1,h2,h3,l0,l1,l2,l3;
        split1(o0,h0,l0); split1(o1,h1,l1); split1(o2,h2,l2); split1(o3,h3,l3);
        bf162* ph = (bf162*)(oh + (size_t)row * EE + t * 4);
        bf162* pl = (bf162*)(ol + (size_t)row * EE + t * 4);
        ph[0] = bf162{h0,h1}; ph[1] = bf162{h2,h3};
        pl[0] = bf162{l0,l1}; pl[1] = bf162{l2,l3};
    }
}

// ---------------- host launch ----------------
#define SMEMB(MFRAG) (3 * (2 * ((MFRAG)*32*80) + 2 * (128*80)))

extern "C" void kernel_launch(void* const* d_in, const int* in_sizes, int n_in,
                              void* d_out, int out_size) {
    const float* x     = (const float*)d_in[0];
    const float* in_w  = (const float*)d_in[1];
    const float* in_b  = (const float*)d_in[2];
    const float* out_w = (const float*)d_in[3];
    const float* out_b = (const float*)d_in[4];
    const float* ln1w  = (const float*)d_in[5];
    const float* ln1b  = (const float*)d_in[6];
    const float* ln2w  = (const float*)d_in[7];
    const float* ln2b  = (const float*)d_in[8];
    const float* w1    = (const float*)d_in[9];
    const float* b1    = (const float*)d_in[10];
    const float* w2    = (const float*)d_in[11];
    const float* b2    = (const float*)d_in[12];
    float* out = (float*)d_out;

    static bf16 *p_proj_h=nullptr, *p_proj_l, *p_ctx_h, *p_ctx_l,
                *p_x1h, *p_x1l, *p_hh, *p_hl, *p_wh, *p_wl;
    static float *p_qkv, *p_x1f, *p_t0;
    if (!p_proj_h) {
        cudaGetSymbolAddress((void**)&p_proj_h, g_proj_h);
        cudaGetSymbolAddress((void**)&p_proj_l, g_proj_l);
        cudaGetSymbolAddress((void**)&p_qkv,   g_qkv);
        cudaGetSymbolAddress((void**)&p_ctx_h, g_ctx_h);
        cudaGetSymbolAddress((void**)&p_ctx_l, g_ctx_l);
        cudaGetSymbolAddress((void**)&p_x1f,   g_x1f);
        cudaGetSymbolAddress((void**)&p_x1h,   g_x1_h);
        cudaGetSymbolAddress((void**)&p_x1l,   g_x1_l);
        cudaGetSymbolAddress((void**)&p_hh,    g_hh);
        cudaGetSymbolAddress((void**)&p_hl,    g_hl);
        cudaGetSymbolAddress((void**)&p_t0,    g_t0);
        cudaGetSymbolAddress((void**)&p_wh,    g_wh);
        cudaGetSymbolAddress((void**)&p_wl,    g_wl);
        cudaFuncSetAttribute(gemm_mma<4,0,false>, cudaFuncAttributeMaxDynamicSharedMemorySize, SMEMB(4));
        cudaFuncSetAttribute(gemm_mma<4,1,true >, cudaFuncAttributeMaxDynamicSharedMemorySize, SMEMB(4));
        cudaFuncSetAttribute(gemm_mma<2,0,false>, cudaFuncAttributeMaxDynamicSharedMemorySize, SMEMB(2));
    }

    // weight splits (one kernel)
    split_all_kernel<<<(W_TOTAL/4 + 255)/256, 256>>>(in_w, out_w, w1, w2, p_wh, p_wl);

    // proj (prefix-cos) with bf16 hi/lo split
    const int ngroups = MROWS * EE / 8;
    proj_kernel<<<(ngroups + 255)/256, 256>>>(x, p_proj_h, p_proj_l, ngroups);

    // qkv = proj @ in_w^T + in_b  (2048 x 1536, K=512) -> fp32
    gemm_mma<4,0,false><<<dim3(QKVN/128, MROWS/128), 256, SMEMB(4)>>>(
        p_proj_h, p_proj_l, p_wh + W_INW, p_wl + W_INW, in_b,
        p_qkv, nullptr, nullptr, QKVN, EE);

    // attention -> ctx hi/lo
    attn_kernel<<<BBATCH * HH, SS>>>(p_qkv, p_ctx_h, p_ctx_l);

    // attn_out = ctx @ out_w^T + out_b (2048 x 512, K=512) -> t0 fp32 ; BM=64 grid=128
    gemm_mma<2,0,false><<<dim3(EE/128, MROWS/64), 256, SMEMB(2)>>>(
        p_ctx_h, p_ctx_l, p_wh + W_OUTW, p_wl + W_OUTW, out_b,
        p_t0, nullptr, nullptr, EE, EE);

    // x1 = LN(x + attn_out) -> fp32 + hi/lo
    add_ln_kernel<true><<<MROWS, 128>>>(x, p_t0, ln1w, ln1b, p_x1f, p_x1h, p_x1l);

    // h = relu(x1 @ w1^T + b1) (2048 x 2048, K=512) -> hi/lo only
    gemm_mma<4,1,true><<<dim3(FFNN/128, MROWS/128), 256, SMEMB(4)>>>(
        p_x1h, p_x1l, p_wh + W_W1, p_wl + W_W1, b1,
        nullptr, p_hh, p_hl, FFNN, EE);

    // ffn_out = h @ w2^T + b2 (2048 x 512, K=2048) -> t0 fp32 ; BM=64 grid=128
    gemm_mma<2,0,false><<<dim3(EE/128, MROWS/64), 256, SMEMB(2)>>>(
        p_hh, p_hl, p_wh + W_W2, p_wl + W_W2, b2,
        p_t0, nullptr, nullptr, EE, FFNN);

    // out = LN(x1 + ffn_out)
    add_ln_kernel<false><<<MROWS, 128>>>(p_x1f, p_t0, ln2w, ln2b, out, nullptr, nullptr);

    (void)in_sizes; (void)n_in; (void)out_size;
}